// round 3
// baseline (speedup 1.0000x reference)
#include <cuda_runtime.h>
#include <cstdint>

#define N_NODES 50000
#define N_EDGES 800000
#define MT  192     // rows per tile
#define NTH 192     // threads per block (6 warps, 32 rows each)

// ---------------- scratch (static device allocation) ---------------------------
__device__ float g_summed[N_NODES * 64];
__device__ float g_counts[N_NODES];

// ---------------- helpers -------------------------------------------------------
__device__ __forceinline__ uint32_t to_tf32(float f) {
    uint32_t r; asm("cvt.rna.tf32.f32 %0, %1;" : "=r"(r) : "f"(f)); return r;
}
__device__ __forceinline__ void red4(float* a, float4 v) {
    asm volatile("red.global.add.v4.f32 [%0], {%1,%2,%3,%4};"
                 :: "l"(a), "f"(v.x), "f"(v.y), "f"(v.z), "f"(v.w) : "memory");
}
// m16n8k8 tf32 MMA. Fragment layout (g = lane>>2, c = lane&3):
//   A: a0=A[g][c]  a1=A[g+8][c]  a2=A[g][c+4]  a3=A[g+8][c+4]
//   B: b0=B[c][g]  b1=B[c+4][g]            (B is k8 x n8)
//   D: d0=D[g][2c] d1=D[g][2c+1] d2=D[g+8][2c] d3=D[g+8][2c+1]
__device__ __forceinline__ void mma8(float d[4], const uint32_t a[4],
                                     uint32_t b0, uint32_t b1) {
    asm("mma.sync.aligned.m16n8k8.row.col.f32.tf32.tf32.f32 "
        "{%0,%1,%2,%3}, {%4,%5,%6,%7}, {%8,%9}, {%0,%1,%2,%3};"
        : "+f"(d[0]), "+f"(d[1]), "+f"(d[2]), "+f"(d[3])
        : "r"(a[0]), "r"(a[1]), "r"(a[2]), "r"(a[3]), "r"(b0), "r"(b1));
}

// ---------------- smem layout (float offsets) ------------------------------------
// A tile: 192 x 132 (stride 132: 132%32==4 -> conflict-free A-frag LDS.32)
// hidden/D overlay A with stride 68 (68%32==4, per-warp-private rows)
#define SA_F    0
#define SW1_F   (MT * 132)            // 25344 : W1 frags 16kc*8nb*32t*4 = 16384 f
#define SW2_F   (SW1_F + 16384)       // 41728 : W2 frags  8kc*8nb*32t*4 =  8192 f
#define SBA_F   (SW2_F + 8192)        // 49920
#define SBB_F   (SBA_F + 64)          // 49984
#define SROW_F  (SBB_F + 64)          // 50048
#define SCOL_F  (SROW_F + MT)         // 50240
#define SMEM_FLOATS (SCOL_F + MT)     // 50432
#define SMEM_BYTES  (SMEM_FLOATS * 4) // 201728 bytes

// ---------------- shared GEMM core ------------------------------------------------
// Each warp: 32 rows (r0 = wid*32 + g), 64 cols (8 n-blocks), KC k-chunks of 8.
// Weights pre-permuted: sWf[(kc*8+nb)*32 + lane] = {b0_hi, b1_hi, b0_lo, b1_lo}.
template <int KC>
__device__ __forceinline__ void gemm(const float* __restrict__ sIn, int lds,
                                     const uint4* __restrict__ sWf,
                                     int r0, int lane, float acc[2][8][4]) {
#pragma unroll
    for (int g = 0; g < 2; ++g)
#pragma unroll
        for (int nb = 0; nb < 8; ++nb)
#pragma unroll
            for (int j = 0; j < 4; ++j) acc[g][nb][j] = 0.0f;

    const int tc = lane & 3;
#pragma unroll 2
    for (int kc = 0; kc < KC; ++kc) {
        uint32_t a[2][4];
        const float* p = sIn + kc * 8 + tc;
#pragma unroll
        for (int g = 0; g < 2; ++g) {
            const float* q = p + (r0 + g * 16) * lds;
            a[g][0] = __float_as_uint(q[0]);
            a[g][1] = __float_as_uint(q[8 * lds]);
            a[g][2] = __float_as_uint(q[4]);
            a[g][3] = __float_as_uint(q[8 * lds + 4]);
        }
#pragma unroll
        for (int nb = 0; nb < 8; ++nb) {
            uint4 B = sWf[(kc * 8 + nb) * 32 + lane];
            mma8(acc[0][nb], a[0], B.x, B.y);   // W_hi
            mma8(acc[0][nb], a[0], B.z, B.w);   // W_lo
            mma8(acc[1][nb], a[1], B.x, B.y);
            mma8(acc[1][nb], a[1], B.z, B.w);
        }
    }
}

// ---------------- fused GNN pass ---------------------------------------------------
template <bool EDGE>
__global__ void __launch_bounds__(NTH, 1)
gnn_pass(const float* __restrict__ x,
         const void* __restrict__ ei,
         const float* __restrict__ ea,
         const float* __restrict__ Wa, const float* __restrict__ ba,
         const float* __restrict__ Wb, const float* __restrict__ bb,
         float* __restrict__ outp)
{
    extern __shared__ float sm[];
    float* sA  = sm + SA_F;
    uint4* sW1 = reinterpret_cast<uint4*>(sm + SW1_F);
    uint4* sW2 = reinterpret_cast<uint4*>(sm + SW2_F);
    float* sBa = sm + SBA_F;
    float* sBb = sm + SBB_F;
    int*   sRow = reinterpret_cast<int*>(sm + SROW_F);
    int*   sCol = reinterpret_cast<int*>(sm + SCOL_F);

    const int tid = threadIdx.x, wid = tid >> 5, lane = tid & 31;
    const int tg = lane >> 2, tc = lane & 3;
    const int r0 = wid * 32 + tg;

    // ---- stage weights into fragment layout, split hi/lo (exact weights) ----
    for (int i = tid; i < 4096; i += NTH) {             // W1: 16 kc
        const int kc = i >> 8, nb = (i >> 5) & 7, t = i & 31;
        const int k0 = kc * 8 + (t & 3), n = nb * 8 + (t >> 2);
        const float w0 = Wa[k0 * 64 + n], w1 = Wa[(k0 + 4) * 64 + n];
        uint4 fr;
        fr.x = to_tf32(w0); fr.y = to_tf32(w1);
        fr.z = to_tf32(w0 - __uint_as_float(fr.x));
        fr.w = to_tf32(w1 - __uint_as_float(fr.y));
        sW1[i] = fr;
    }
    for (int i = tid; i < 2048; i += NTH) {             // W2: 8 kc
        const int kc = i >> 8, nb = (i >> 5) & 7, t = i & 31;
        const int k0 = kc * 8 + (t & 3), n = nb * 8 + (t >> 2);
        const float w0 = Wb[k0 * 64 + n], w1 = Wb[(k0 + 4) * 64 + n];
        uint4 fr;
        fr.x = to_tf32(w0); fr.y = to_tf32(w1);
        fr.z = to_tf32(w0 - __uint_as_float(fr.x));
        fr.w = to_tf32(w1 - __uint_as_float(fr.y));
        sW2[i] = fr;
    }
    if (tid < 64) { sBa[tid] = ba[tid]; sBb[tid] = bb[tid]; }
    __syncthreads();

    const int total  = EDGE ? N_EDGES : N_NODES;
    const int ntiles = (total + MT - 1) / MT;

    for (int tile = blockIdx.x; tile < ntiles; tile += gridDim.x) {
        const int base = tile * MT;
        __syncthreads();  // previous tile's smem fully consumed

        // ---- stage indices + degree counts (edge pass) ----
        if (EDGE) {
            {
                const int ge = base + tid;
                const int* e32 = reinterpret_cast<const int*>(ei);
                // dtype sniff: int64 edge_index has zero high words for small values
                const bool is64 = ((e32[1] | e32[3] | e32[5] | e32[7]) == 0);
                int r = 0, c = 0;
                if (ge < N_EDGES) {
                    if (is64) {
                        const long long* e64 = reinterpret_cast<const long long*>(ei);
                        r = (int)e64[ge]; c = (int)e64[N_EDGES + ge];
                    } else {
                        r = e32[ge]; c = e32[N_EDGES + ge];
                    }
                    atomicAdd(&g_counts[r], 1.0f);
                }
                sRow[tid] = r; sCol[tid] = c;
            }
            __syncthreads();
        }

        // ---- gather A tile [192 x 128] -> tf32(rna), row-major stride 132 ----
        for (int i = tid; i < MT * 32; i += NTH) {
            const int row = i >> 5, q = i & 31;
            float4 v;
            if (EDGE) {
                if (q < 16) {
                    v = reinterpret_cast<const float4*>(x)[sCol[row] * 16 + q];
                } else {
                    const int ge = base + row;
                    const int gs = ge < N_EDGES ? ge : N_EDGES - 1;
                    v = reinterpret_cast<const float4*>(ea)[gs * 16 + (q - 16)];
                }
            } else {
                const int gi = base + row;
                const int n = gi < N_NODES ? gi : N_NODES - 1;
                if (q < 16) {
                    v = reinterpret_cast<const float4*>(x)[n * 16 + q];
                } else {
                    const float s = 1.0f / fmaxf(g_counts[n], 1.0f);
                    v = reinterpret_cast<const float4*>(g_summed)[n * 16 + (q - 16)];
                    v.x *= s; v.y *= s; v.z *= s; v.w *= s;
                }
            }
            uint4 t4;
            t4.x = to_tf32(v.x); t4.y = to_tf32(v.y);
            t4.z = to_tf32(v.z); t4.w = to_tf32(v.w);
            *reinterpret_cast<uint4*>(sA + row * 132 + q * 4) = t4;
        }
        __syncthreads();

        // ---- GEMM1: [192x128] @ [128x64], 16 k-chunks x (hi+lo) ----
        float acc[2][8][4];
        gemm<16>(sA, 132, sW1, r0, lane, acc);
        __syncthreads();  // all A reads done before hidden overlays the buffer

        // ---- epilogue1: relu(acc + ba) -> tf32 hidden, stride 68 (warp-own rows)
        float* sH = sA;
#pragma unroll
        for (int g = 0; g < 2; ++g) {
            const int ra = wid * 32 + g * 16 + tg, rb = ra + 8;
#pragma unroll
            for (int nb = 0; nb < 8; ++nb) {
                const int col = nb * 8 + tc * 2;
                const float2 bi = *reinterpret_cast<const float2*>(sBa + col);
                uint2 pa, pb;
                pa.x = to_tf32(fmaxf(acc[g][nb][0] + bi.x, 0.0f));
                pa.y = to_tf32(fmaxf(acc[g][nb][1] + bi.y, 0.0f));
                pb.x = to_tf32(fmaxf(acc[g][nb][2] + bi.x, 0.0f));
                pb.y = to_tf32(fmaxf(acc[g][nb][3] + bi.y, 0.0f));
                *reinterpret_cast<uint2*>(sH + ra * 68 + col) = pa;
                *reinterpret_cast<uint2*>(sH + rb * 68 + col) = pb;
            }
        }
        __syncwarp();  // in-warp smem visibility for GEMM2 A-frag reads

        // ---- GEMM2: [192x64] @ [64x64], 8 k-chunks x (hi+lo) ----
        float acc2[2][8][4];
        gemm<8>(sH, 68, sW2, r0, lane, acc2);

        // ---- epilogue2 ----
        if (EDGE) {
            // write D(+bias) back over hidden (warp-own rows), then red.v4
            __syncwarp();
#pragma unroll
            for (int g = 0; g < 2; ++g) {
                const int ra = wid * 32 + g * 16 + tg, rb = ra + 8;
#pragma unroll
                for (int nb = 0; nb < 8; ++nb) {
                    const int col = nb * 8 + tc * 2;
                    const float2 bi = *reinterpret_cast<const float2*>(sBb + col);
                    float2 da = make_float2(acc2[g][nb][0] + bi.x, acc2[g][nb][1] + bi.y);
                    float2 db = make_float2(acc2[g][nb][2] + bi.x, acc2[g][nb][3] + bi.y);
                    *reinterpret_cast<float2*>(sH + ra * 68 + col) = da;
                    *reinterpret_cast<float2*>(sH + rb * 68 + col) = db;
                }
            }
            __syncthreads();
            for (int i = tid; i < MT * 16; i += NTH) {
                const int row = i >> 4, q = i & 15;
                if (base + row < N_EDGES) {
                    const float4 v = *reinterpret_cast<const float4*>(sH + row * 68 + q * 4);
                    red4(g_summed + (long long)sRow[row] * 64 + q * 4, v);
                }
            }
        } else {
            // direct store
#pragma unroll
            for (int g = 0; g < 2; ++g) {
                const int ra = wid * 32 + g * 16 + tg, rb = ra + 8;
#pragma unroll
                for (int nb = 0; nb < 8; ++nb) {
                    const int col = nb * 8 + tc * 2;
                    const float2 bi = *reinterpret_cast<const float2*>(sBb + col);
                    if (base + ra < N_NODES) {
                        float2 d = make_float2(acc2[g][nb][0] + bi.x, acc2[g][nb][1] + bi.y);
                        *reinterpret_cast<float2*>(outp + (base + ra) * 64 + col) = d;
                    }
                    if (base + rb < N_NODES) {
                        float2 d = make_float2(acc2[g][nb][2] + bi.x, acc2[g][nb][3] + bi.y);
                        *reinterpret_cast<float2*>(outp + (base + rb) * 64 + col) = d;
                    }
                }
            }
        }
    }
}

// ---------------- launch ------------------------------------------------------------
extern "C" void kernel_launch(void* const* d_in, const int* in_sizes, int n_in,
                              void* d_out, int out_size) {
    const float* x   = reinterpret_cast<const float*>(d_in[0]);
    const void*  ei  = d_in[1];
    const float* ea  = reinterpret_cast<const float*>(d_in[2]);
    const float* W1a = reinterpret_cast<const float*>(d_in[5]);
    const float* b1a = reinterpret_cast<const float*>(d_in[6]);
    const float* W1b = reinterpret_cast<const float*>(d_in[7]);
    const float* b1b = reinterpret_cast<const float*>(d_in[8]);
    const float* W2a = reinterpret_cast<const float*>(d_in[9]);
    const float* b2a = reinterpret_cast<const float*>(d_in[10]);
    const float* W2b = reinterpret_cast<const float*>(d_in[11]);
    const float* b2b = reinterpret_cast<const float*>(d_in[12]);
    float* out = reinterpret_cast<float*>(d_out);

    cudaFuncSetAttribute(gnn_pass<true>,
                         cudaFuncAttributeMaxDynamicSharedMemorySize, SMEM_BYTES);
    cudaFuncSetAttribute(gnn_pass<false>,
                         cudaFuncAttributeMaxDynamicSharedMemorySize, SMEM_BYTES);

    void* gs = nullptr; void* gc = nullptr;
    cudaGetSymbolAddress(&gs, g_summed);
    cudaGetSymbolAddress(&gc, g_counts);
    cudaMemsetAsync(gs, 0, (size_t)N_NODES * 64 * sizeof(float));
    cudaMemsetAsync(gc, 0, (size_t)N_NODES * sizeof(float));

    gnn_pass<true><<<148, NTH, SMEM_BYTES>>>(x, ei, ea, W1a, b1a, W1b, b1b, nullptr);
    gnn_pass<false><<<148, NTH, SMEM_BYTES>>>(x, nullptr, nullptr,
                                              W2a, b2a, W2b, b2b, out);
}

// round 4
// speedup vs baseline: 1.7647x; 1.7647x over previous
#include <cuda_runtime.h>
#include <cstdint>

#define N_NODES 50000
#define N_EDGES 800000
#define MT   96      // rows per tile
#define NTH  384     // 12 warps: wr = wid>>1 (row group 0..5), cg = wid&1 (col half)

// ---------------- scratch (static device allocation) ---------------------------
__device__ float g_summed[N_NODES * 64];
__device__ float g_counts[N_NODES];

// ---------------- helpers -------------------------------------------------------
__device__ __forceinline__ uint32_t to_tf32(float f) {
    uint32_t r; asm("cvt.rna.tf32.f32 %0, %1;" : "=r"(r) : "f"(f)); return r;
}
__device__ __forceinline__ void red4(float* a, float4 v) {
    asm volatile("red.global.add.v4.f32 [%0], {%1,%2,%3,%4};"
                 :: "l"(a), "f"(v.x), "f"(v.y), "f"(v.z), "f"(v.w) : "memory");
}
// m16n8k8 tf32 MMA. g = lane>>2, c = lane&3:
//   A: a0=A[g][c] a1=A[g+8][c] a2=A[g][c+4] a3=A[g+8][c+4]
//   B: b0=B[c][n] b1=B[c+4][n]   (n = lane>>2)
//   D: d0=D[g][2c] d1=D[g][2c+1] d2=D[g+8][2c] d3=D[g+8][2c+1]
__device__ __forceinline__ void mma8(float d[4], const uint32_t a[4],
                                     uint32_t b0, uint32_t b1) {
    asm("mma.sync.aligned.m16n8k8.row.col.f32.tf32.tf32.f32 "
        "{%0,%1,%2,%3}, {%4,%5,%6,%7}, {%8,%9}, {%0,%1,%2,%3};"
        : "+f"(d[0]), "+f"(d[1]), "+f"(d[2]), "+f"(d[3])
        : "r"(a[0]), "r"(a[1]), "r"(a[2]), "r"(a[3]), "r"(b0), "r"(b1));
}

// ---------------- smem layout (float offsets) -------------------------------------
// A tiles stride 132 (132%32==4 -> conflict-free A-frag LDS); hidden overlays A[cur]
// at stride 68; D has its own region (stride 68).
#define SA0_F   0                      // 96*132 = 12672
#define SA1_F   12672                  // 12672
#define SD_F    25344                  // 96*68 = 6528
#define SW1_F   31872                  // 16 kc * 8 nb * 32 * 4 = 16384
#define SW2_F   48256                  // 8192
#define SBA_F   56448                  // 64
#define SBB_F   56512                  // 64
#define SROW_F  56576                  // 3 * 96 int ring
#define SCOL_F  56864                  // 3 * 96 int ring
#define SMEM_FLOATS 57152
#define SMEM_BYTES  (SMEM_FLOATS * 4)  // 228,608 B

// ---------------- index staging (edge pass) ----------------------------------------
__device__ __forceinline__ void load_idx(const void* ei, int tbase, int* rs, int* cs) {
    const int t = threadIdx.x;
    if (t < MT) {
        const int ge = tbase + t;
        int r = 0, c = 0;
        if (ge < N_EDGES) {
            const int* e32 = reinterpret_cast<const int*>(ei);
            // dtype sniff: int64 edge_index has zero high words for small values
            const bool is64 = ((e32[1] | e32[3] | e32[5] | e32[7]) == 0);
            if (is64) {
                const long long* e64 = reinterpret_cast<const long long*>(ei);
                r = (int)e64[ge]; c = (int)e64[N_EDGES + ge];
            } else {
                r = e32[ge]; c = e32[N_EDGES + ge];
            }
            atomicAdd(&g_counts[r], 1.0f);
        }
        rs[t] = r; cs[t] = c;
    }
}

// ---------------- gather (LDG -> regs) and store (cvt -> STS) ----------------------
template <bool EDGE>
__device__ __forceinline__ void gather_regs(int base, const int* cols,
                                            const float* __restrict__ x,
                                            const float* __restrict__ ea,
                                            float4 g[8]) {
#pragma unroll
    for (int it = 0; it < 8; ++it) {
        const int i = it * NTH + threadIdx.x;   // [0, 96*32)
        const int row = i >> 5, q = i & 31;
        float4 v;
        if (EDGE) {
            if (q < 16) {
                v = reinterpret_cast<const float4*>(x)[cols[row] * 16 + q];
            } else {
                const int ge = base + row;
                const int gs = ge < N_EDGES ? ge : N_EDGES - 1;
                v = reinterpret_cast<const float4*>(ea)[gs * 16 + (q - 16)];
            }
        } else {
            const int gi = base + row;
            const int n = gi < N_NODES ? gi : N_NODES - 1;
            if (q < 16) {
                v = reinterpret_cast<const float4*>(x)[n * 16 + q];
            } else {
                const float s = 1.0f / fmaxf(g_counts[n], 1.0f);
                v = reinterpret_cast<const float4*>(g_summed)[n * 16 + (q - 16)];
                v.x *= s; v.y *= s; v.z *= s; v.w *= s;
            }
        }
        g[it] = v;
    }
}

__device__ __forceinline__ void store_regs(float* __restrict__ sA, const float4 g[8]) {
#pragma unroll
    for (int it = 0; it < 8; ++it) {
        const int i = it * NTH + threadIdx.x;
        const int row = i >> 5, q = i & 31;
        uint4 t4;
        t4.x = to_tf32(g[it].x); t4.y = to_tf32(g[it].y);
        t4.z = to_tf32(g[it].z); t4.w = to_tf32(g[it].w);
        *reinterpret_cast<uint4*>(sA + row * 132 + q * 4) = t4;
    }
}

// ---------------- GEMM core --------------------------------------------------------
// Warp: 16 rows (r0 = wr*16 + tg) x 32 cols (4 nb at cg*4+nb). KC k-chunks of 8.
// Weight frags: sWf[(kc*8 + nbg)*32 + lane] = {b0_hi, b1_hi, b0_lo, b1_lo}.
template <int KC>
__device__ __forceinline__ void gemm(const float* __restrict__ sIn, int lds,
                                     const uint4* __restrict__ sWf,
                                     int r0, int lane, int cg, float acc[4][4]) {
#pragma unroll
    for (int nb = 0; nb < 4; ++nb)
#pragma unroll
        for (int j = 0; j < 4; ++j) acc[nb][j] = 0.0f;

    const int tc = lane & 3;
    const float* p0 = sIn + r0 * lds;
#pragma unroll 4
    for (int kc = 0; kc < KC; ++kc) {
        const float* q = p0 + kc * 8 + tc;
        uint32_t a[4];
        a[0] = __float_as_uint(q[0]);
        a[1] = __float_as_uint(q[8 * lds]);
        a[2] = __float_as_uint(q[4]);
        a[3] = __float_as_uint(q[8 * lds + 4]);
#pragma unroll
        for (int nb = 0; nb < 4; ++nb) {
            const uint4 B = sWf[(kc * 8 + cg * 4 + nb) * 32 + lane];
            mma8(acc[nb], a, B.x, B.y);   // W_hi
            mma8(acc[nb], a, B.z, B.w);   // W_lo (exact weights)
        }
    }
}

// ---------------- fused GNN pass -----------------------------------------------------
template <bool EDGE>
__global__ void __launch_bounds__(NTH, 1)
gnn_pass(const float* __restrict__ x,
         const void* __restrict__ ei,
         const float* __restrict__ ea,
         const float* __restrict__ Wa, const float* __restrict__ ba,
         const float* __restrict__ Wb, const float* __restrict__ bb,
         float* __restrict__ outp)
{
    extern __shared__ float sm[];
    float* sA0 = sm + SA0_F;
    float* sA1 = sm + SA1_F;
    float* sD  = sm + SD_F;
    uint4* sW1 = reinterpret_cast<uint4*>(sm + SW1_F);
    uint4* sW2 = reinterpret_cast<uint4*>(sm + SW2_F);
    float* sBa = sm + SBA_F;
    float* sBb = sm + SBB_F;
    int*   sRow = reinterpret_cast<int*>(sm + SROW_F);
    int*   sCol = reinterpret_cast<int*>(sm + SCOL_F);

    const int tid = threadIdx.x, wid = tid >> 5, lane = tid & 31;
    const int tg = lane >> 2, tc = lane & 3;
    const int wr = wid >> 1, cg = wid & 1;
    const int r0 = wr * 16 + tg;

    // ---- stage weights into fragment layout, hi/lo split (exact weights) ----
    for (int i = tid; i < 4096; i += NTH) {             // W1: 16 kc x 8 nb
        const int kc = i >> 8, nb = (i >> 5) & 7, t = i & 31;
        const int k0 = kc * 8 + (t & 3), n = nb * 8 + (t >> 2);
        const float w0 = Wa[k0 * 64 + n], w1 = Wa[(k0 + 4) * 64 + n];
        uint4 fr;
        fr.x = to_tf32(w0); fr.y = to_tf32(w1);
        fr.z = to_tf32(w0 - __uint_as_float(fr.x));
        fr.w = to_tf32(w1 - __uint_as_float(fr.y));
        sW1[i] = fr;
    }
    for (int i = tid; i < 2048; i += NTH) {             // W2: 8 kc x 8 nb
        const int kc = i >> 8, nb = (i >> 5) & 7, t = i & 31;
        const int k0 = kc * 8 + (t & 3), n = nb * 8 + (t >> 2);
        const float w0 = Wb[k0 * 64 + n], w1 = Wb[(k0 + 4) * 64 + n];
        uint4 fr;
        fr.x = to_tf32(w0); fr.y = to_tf32(w1);
        fr.z = to_tf32(w0 - __uint_as_float(fr.x));
        fr.w = to_tf32(w1 - __uint_as_float(fr.y));
        sW2[i] = fr;
    }
    if (tid < 64) { sBa[tid] = ba[tid]; sBb[tid] = bb[tid]; }

    const int total  = EDGE ? N_EDGES : N_NODES;
    const int ntiles = (total + MT - 1) / MT;
    const int S = gridDim.x;
    const int t0 = blockIdx.x;

    // ---- prologue: indices for tiles j=0,1; gather+store tile 0 ----
    if (EDGE) {
        if (t0 < ntiles)     load_idx(ei, t0 * MT,       sRow,      sCol);
        if (t0 + S < ntiles) load_idx(ei, (t0 + S) * MT, sRow + 96, sCol + 96);
    }
    __syncthreads();

    float4 g[8];
    if (t0 < ntiles) {
        gather_regs<EDGE>(t0 * MT, sCol, x, ea, g);
        store_regs(sA0, g);
    }
    __syncthreads();

    for (int j = 0; t0 + j * S < ntiles; ++j) {
        const int tile = t0 + j * S;
        const int base = tile * MT;
        float* sAc = (j & 1) ? sA1 : sA0;
        float* sAn = (j & 1) ? sA0 : sA1;
        const bool hasNext = (tile + S) < ntiles;

        // ---- prefetch: issue next tile's gather LDGs (regs), idx for j+2 ----
        if (hasNext)
            gather_regs<EDGE>((tile + S) * MT, sCol + ((j + 1) % 3) * 96, x, ea, g);
        if (EDGE && (tile + 2 * S) < ntiles)
            load_idx(ei, (tile + 2 * S) * MT,
                     sRow + ((j + 2) % 3) * 96, sCol + ((j + 2) % 3) * 96);

        // ---- GEMM1: [96x128] @ [128x64] (hi+lo) ----
        float acc[4][4];
        gemm<16>(sAc, 132, sW1, r0, lane, cg, acc);
        __syncthreads();   // A[cur] reads done -> hidden overlay safe

        // ---- epilogue1: relu(acc + ba) -> tf32 hidden (overlay A[cur], stride 68)
        float* sH = sAc;
        {
            const int rowa = wr * 16 + tg, rowb = rowa + 8;
#pragma unroll
            for (int nb = 0; nb < 4; ++nb) {
                const int col = cg * 32 + nb * 8 + tc * 2;
                const float2 bi = *reinterpret_cast<const float2*>(sBa + col);
                uint2 pa, pb;
                pa.x = to_tf32(fmaxf(acc[nb][0] + bi.x, 0.0f));
                pa.y = to_tf32(fmaxf(acc[nb][1] + bi.y, 0.0f));
                pb.x = to_tf32(fmaxf(acc[nb][2] + bi.x, 0.0f));
                pb.y = to_tf32(fmaxf(acc[nb][3] + bi.y, 0.0f));
                *reinterpret_cast<uint2*>(sH + rowa * 68 + col) = pa;
                *reinterpret_cast<uint2*>(sH + rowb * 68 + col) = pb;
            }
        }
        __syncthreads();   // hidden visible to both col-half warps

        // ---- drain prefetched regs into A[next] (dead buffer this iter) ----
        if (hasNext) store_regs(sAn, g);

        // ---- GEMM2: [96x64] @ [64x64] (hi+lo) ----
        float acc2[4][4];
        gemm<8>(sH, 68, sW2, r0, lane, cg, acc2);

        // ---- epilogue2 ----
        if (EDGE) {
            const int rowa = wr * 16 + tg, rowb = rowa + 8;
#pragma unroll
            for (int nb = 0; nb < 4; ++nb) {
                const int col = cg * 32 + nb * 8 + tc * 2;
                const float2 bi = *reinterpret_cast<const float2*>(sBb + col);
                float2 da = make_float2(acc2[nb][0] + bi.x, acc2[nb][1] + bi.y);
                float2 db = make_float2(acc2[nb][2] + bi.x, acc2[nb][3] + bi.y);
                *reinterpret_cast<float2*>(sD + rowa * 68 + col) = da;
                *reinterpret_cast<float2*>(sD + rowb * 68 + col) = db;
            }
            __syncthreads();
            const int* rows = sRow + (j % 3) * 96;
#pragma unroll
            for (int it = 0; it < 4; ++it) {
                const int i = it * NTH + tid;   // [0, 96*16)
                const int row = i >> 4, q = i & 15;
                if (base + row < N_EDGES) {
                    const float4 v = *reinterpret_cast<const float4*>(sD + row * 68 + q * 4);
                    red4(g_summed + (size_t)rows[row] * 64 + q * 4, v);
                }
            }
        } else {
            const int rowa = wr * 16 + tg, rowb = rowa + 8;
#pragma unroll
            for (int nb = 0; nb < 4; ++nb) {
                const int col = cg * 32 + nb * 8 + tc * 2;
                const float2 bi = *reinterpret_cast<const float2*>(sBb + col);
                const int ga = base + rowa, gb = base + rowb;
                if (ga < N_NODES) {
                    float2 d = make_float2(acc2[nb][0] + bi.x, acc2[nb][1] + bi.y);
                    *reinterpret_cast<float2*>(outp + (size_t)ga * 64 + col) = d;
                }
                if (gb < N_NODES) {
                    float2 d = make_float2(acc2[nb][2] + bi.x, acc2[nb][3] + bi.y);
                    *reinterpret_cast<float2*>(outp + (size_t)gb * 64 + col) = d;
                }
            }
        }
        __syncthreads();   // A[next] + idx ring + sD safe for next iteration
    }
}

// ---------------- launch --------------------------------------------------------------
extern "C" void kernel_launch(void* const* d_in, const int* in_sizes, int n_in,
                              void* d_out, int out_size) {
    const float* x   = reinterpret_cast<const float*>(d_in[0]);
    const void*  ei  = d_in[1];
    const float* ea  = reinterpret_cast<const float*>(d_in[2]);
    const float* W1a = reinterpret_cast<const float*>(d_in[5]);
    const float* b1a = reinterpret_cast<const float*>(d_in[6]);
    const float* W1b = reinterpret_cast<const float*>(d_in[7]);
    const float* b1b = reinterpret_cast<const float*>(d_in[8]);
    const float* W2a = reinterpret_cast<const float*>(d_in[9]);
    const float* b2a = reinterpret_cast<const float*>(d_in[10]);
    const float* W2b = reinterpret_cast<const float*>(d_in[11]);
    const float* b2b = reinterpret_cast<const float*>(d_in[12]);
    float* out = reinterpret_cast<float*>(d_out);

    cudaFuncSetAttribute(gnn_pass<true>,
                         cudaFuncAttributeMaxDynamicSharedMemorySize, SMEM_BYTES);
    cudaFuncSetAttribute(gnn_pass<false>,
                         cudaFuncAttributeMaxDynamicSharedMemorySize, SMEM_BYTES);

    void* gs = nullptr; void* gc = nullptr;
    cudaGetSymbolAddress(&gs, g_summed);
    cudaGetSymbolAddress(&gc, g_counts);
    cudaMemsetAsync(gs, 0, (size_t)N_NODES * 64 * sizeof(float));
    cudaMemsetAsync(gc, 0, (size_t)N_NODES * sizeof(float));

    gnn_pass<true><<<148, NTH, SMEM_BYTES>>>(x, ei, ea, W1a, b1a, W1b, b1b, nullptr);
    gnn_pass<false><<<148, NTH, SMEM_BYTES>>>(x, nullptr, nullptr,
                                              W2a, b2a, W2b, b2b, out);
}

// round 5
// speedup vs baseline: 2.6875x; 1.5230x over previous
#include <cuda_runtime.h>
#include <cstdint>

#define N_NODES 50000
#define N_EDGES 800000
#define NTH  256          // 4 warp-pairs per block
#define NBLK 296          // 2 blocks per SM

// ---------------- scratch (static device allocation) ---------------------------
__device__ float g_summed[N_NODES * 64];
__device__ float g_counts[N_NODES];

// ---------------- helpers -------------------------------------------------------
__device__ __forceinline__ uint32_t to_tf32(float f) {
    uint32_t r; asm("cvt.rna.tf32.f32 %0, %1;" : "=r"(r) : "f"(f)); return r;
}
__device__ __forceinline__ void red4(float* a, float4 v) {
    asm volatile("red.global.add.v4.f32 [%0], {%1,%2,%3,%4};"
                 :: "l"(a), "f"(v.x), "f"(v.y), "f"(v.z), "f"(v.w) : "memory");
}
__device__ __forceinline__ void barp(int id) {
    asm volatile("bar.sync %0, 64;" :: "r"(id) : "memory");
}
// m16n8k8 tf32 MMA. g = lane>>2, c = lane&3:
//   A: a0=A[g][c] a1=A[g+8][c] a2=A[g][c+4] a3=A[g+8][c+4]
//   B: b0=B[c][n] b1=B[c+4][n]   (n = lane>>2)
//   D: d0=D[g][2c] d1=D[g][2c+1] d2=D[g+8][2c] d3=D[g+8][2c+1]
__device__ __forceinline__ void mma8(float d[4], const uint32_t a[4],
                                     uint32_t b0, uint32_t b1) {
    asm("mma.sync.aligned.m16n8k8.row.col.f32.tf32.tf32.f32 "
        "{%0,%1,%2,%3}, {%4,%5,%6,%7}, {%8,%9}, {%0,%1,%2,%3};"
        : "+f"(d[0]), "+f"(d[1]), "+f"(d[2]), "+f"(d[3])
        : "r"(a[0]), "r"(a[1]), "r"(a[2]), "r"(a[3]), "r"(b0), "r"(b1));
}

// ---------------- smem layout (float offsets) -------------------------------------
// Weights single tf32, fragment layout: sW[(kc*8+nb)*32 + lane] = {b0, b1} (uint2)
#define SW1_F   0                       // 16kc*8nb*32*2 = 8192 f (32KB)
#define SW2_F   8192                    // 4096 f (16KB)
#define SBA_F   12288                   // 64
#define SBB_F   12352                   // 64
#define PAIR_F  12416
// per pair: A 16x132 (2112 f), H/D 16x68 (1088 f), rowRing 48, colRing 48
#define PPF     3296
#define SMEM_FLOATS (PAIR_F + 4 * PPF)  // 25600
#define SMEM_BYTES  (SMEM_FLOATS * 4)   // 102400 B -> 2 blocks/SM

// ---------------- per-pair index staging (edge pass) --------------------------------
__device__ __forceinline__ void load_idx16(const void* ei, int tbase,
                                           int* rs, int* cs, int pt) {
    if (pt < 16) {
        const int ge = tbase + pt;
        const int* e32 = reinterpret_cast<const int*>(ei);
        // dtype sniff: int64 edge_index has zero high words for small values
        const bool is64 = ((e32[1] | e32[3] | e32[5] | e32[7]) == 0);
        int r, c;
        if (is64) {
            const long long* e64 = reinterpret_cast<const long long*>(ei);
            r = (int)e64[ge]; c = (int)e64[N_EDGES + ge];
        } else {
            r = e32[ge]; c = e32[N_EDGES + ge];
        }
        atomicAdd(&g_counts[r], 1.0f);
        rs[pt] = r; cs[pt] = c;
    }
}

// ---------------- per-pair gather (LDG -> regs) / store (cvt -> STS) ----------------
template <bool EDGE>
__device__ __forceinline__ void gather16(int base, const int* cols,
                                         const float* __restrict__ x,
                                         const float* __restrict__ ea,
                                         float4 g[8], int pt) {
#pragma unroll
    for (int it = 0; it < 8; ++it) {
        const int i = it * 64 + pt;      // [0, 16*32)
        const int row = i >> 5, q = i & 31;
        float4 v;
        if (EDGE) {
            if (q < 16) v = reinterpret_cast<const float4*>(x)[cols[row] * 16 + q];
            else        v = reinterpret_cast<const float4*>(ea)[(size_t)(base + row) * 16 + (q - 16)];
        } else {
            const int n = base + row;
            if (q < 16) v = reinterpret_cast<const float4*>(x)[n * 16 + q];
            else {
                const float s = 1.0f / fmaxf(g_counts[n], 1.0f);
                v = reinterpret_cast<const float4*>(g_summed)[n * 16 + (q - 16)];
                v.x *= s; v.y *= s; v.z *= s; v.w *= s;
            }
        }
        g[it] = v;
    }
}

__device__ __forceinline__ void store16(float* __restrict__ sA, const float4 g[8], int pt) {
#pragma unroll
    for (int it = 0; it < 8; ++it) {
        const int i = it * 64 + pt;
        const int row = i >> 5, q = i & 31;
        uint4 t4;
        t4.x = to_tf32(g[it].x); t4.y = to_tf32(g[it].y);
        t4.z = to_tf32(g[it].z); t4.w = to_tf32(g[it].w);
        *reinterpret_cast<uint4*>(sA + row * 132 + q * 4) = t4;
    }
}

// ---------------- GEMM core: warp = 16 rows x 32 cols -------------------------------
template <int KC>
__device__ __forceinline__ void gemm(const float* __restrict__ sIn, int lds,
                                     const uint2* __restrict__ sWf,
                                     int tg, int tc, int lane, int cg, float acc[4][4]) {
#pragma unroll
    for (int nb = 0; nb < 4; ++nb)
#pragma unroll
        for (int j = 0; j < 4; ++j) acc[nb][j] = 0.0f;

    const float* p0 = sIn + tg * lds;
#pragma unroll 4
    for (int kc = 0; kc < KC; ++kc) {
        const float* q = p0 + kc * 8 + tc;
        uint32_t a[4];
        a[0] = __float_as_uint(q[0]);
        a[1] = __float_as_uint(q[8 * lds]);
        a[2] = __float_as_uint(q[4]);
        a[3] = __float_as_uint(q[8 * lds + 4]);
#pragma unroll
        for (int nb = 0; nb < 4; ++nb) {
            const uint2 B = sWf[(kc * 8 + cg * 4 + nb) * 32 + lane];
            mma8(acc[nb], a, B.x, B.y);
        }
    }
}

// ---------------- fused GNN pass ------------------------------------------------------
template <bool EDGE>
__global__ void __launch_bounds__(NTH, 2)
gnn_pass(const float* __restrict__ x,
         const void* __restrict__ ei,
         const float* __restrict__ ea,
         const float* __restrict__ Wa, const float* __restrict__ ba,
         const float* __restrict__ Wb, const float* __restrict__ bb,
         float* __restrict__ outp)
{
    extern __shared__ float sm[];
    uint2* sW1 = reinterpret_cast<uint2*>(sm + SW1_F);
    uint2* sW2 = reinterpret_cast<uint2*>(sm + SW2_F);
    float* sBa = sm + SBA_F;
    float* sBb = sm + SBB_F;

    const int tid = threadIdx.x, lane = tid & 31;
    const int tg = lane >> 2, tc = lane & 3;
    const int pr = tid >> 6;        // pair 0..3
    const int pt = tid & 63;        // thread within pair
    const int cg = (tid >> 5) & 1;  // col half within pair
    const int barid = pr + 1;

    float* sA   = sm + PAIR_F + pr * PPF;
    float* sH   = sA + 2112;
    int*   sRowR = reinterpret_cast<int*>(sH + 1088);  // 3 x 16 ring
    int*   sColR = sRowR + 48;

    // ---- stage weights (single tf32) + biases, block-wide once ----
    for (int i = tid; i < 4096; i += NTH) {             // W1: 16kc x 8nb x 32
        const int kc = i >> 8, nb = (i >> 5) & 7, t = i & 31;
        const int k0 = kc * 8 + (t & 3), n = nb * 8 + (t >> 2);
        uint2 fr;
        fr.x = to_tf32(Wa[k0 * 64 + n]);
        fr.y = to_tf32(Wa[(k0 + 4) * 64 + n]);
        sW1[i] = fr;
    }
    for (int i = tid; i < 2048; i += NTH) {             // W2: 8kc x 8nb x 32
        const int kc = i >> 8, nb = (i >> 5) & 7, t = i & 31;
        const int k0 = kc * 8 + (t & 3), n = nb * 8 + (t >> 2);
        uint2 fr;
        fr.x = to_tf32(Wb[k0 * 64 + n]);
        fr.y = to_tf32(Wb[(k0 + 4) * 64 + n]);
        sW2[i] = fr;
    }
    if (tid < 64) { sBa[tid] = ba[tid]; sBb[tid] = bb[tid]; }
    __syncthreads();   // last block-wide sync; pairs free-run below

    const int NP = gridDim.x * 4;            // total pairs
    const int gp = blockIdx.x * 4 + pr;      // this pair's id
    const int total  = EDGE ? N_EDGES : N_NODES;
    const int ntiles = total >> 4;           // exact: 50000 / 3125

    // ---- prologue: idx for tiles 0,1; gather+store tile 0 ----
    if (EDGE) {
        if (gp < ntiles)      load_idx16(ei, gp * 16, sRowR, sColR, pt);
        if (gp + NP < ntiles) load_idx16(ei, (gp + NP) * 16, sRowR + 16, sColR + 16, pt);
    }
    barp(barid);
    float4 g[8];
    if (gp < ntiles) {
        gather16<EDGE>(gp * 16, sColR, x, ea, g, pt);
        store16(sA, g, pt);
    }
    barp(barid);

    for (int j = 0; gp + j * NP < ntiles; ++j) {
        const int tile = gp + j * NP;
        const int base = tile * 16;
        const bool hasNext = (tile + NP) < ntiles;

        // ---- prefetch next tile's gather (regs) + idx two ahead ----
        if (hasNext)
            gather16<EDGE>((tile + NP) * 16, sColR + ((j + 1) % 3) * 16, x, ea, g, pt);
        if (EDGE && (tile + 2 * NP) < ntiles)
            load_idx16(ei, (tile + 2 * NP) * 16,
                       sRowR + ((j + 2) % 3) * 16, sColR + ((j + 2) % 3) * 16, pt);

        // ---- GEMM1: [16x128] @ [128x64] ----
        float acc[4][4];
        gemm<16>(sA, 132, sW1, tg, tc, lane, cg, acc);

        // ---- epilogue1: relu(acc+ba) -> tf32 hidden (own 32 cols) ----
#pragma unroll
        for (int nb = 0; nb < 4; ++nb) {
            const int col = cg * 32 + nb * 8 + tc * 2;
            const float2 bi = *reinterpret_cast<const float2*>(sBa + col);
            uint2 pa, pb;
            pa.x = to_tf32(fmaxf(acc[nb][0] + bi.x, 0.0f));
            pa.y = to_tf32(fmaxf(acc[nb][1] + bi.y, 0.0f));
            pb.x = to_tf32(fmaxf(acc[nb][2] + bi.x, 0.0f));
            pb.y = to_tf32(fmaxf(acc[nb][3] + bi.y, 0.0f));
            *reinterpret_cast<uint2*>(sH + tg * 68 + col)       = pa;
            *reinterpret_cast<uint2*>(sH + (tg + 8) * 68 + col) = pb;
        }
        barp(barid);   // A reads done (refill safe) + H complete (GEMM2 safe)

        // ---- refill A with prefetched next tile ----
        if (hasNext) store16(sA, g, pt);

        // ---- GEMM2: [16x64] @ [64x64] ----
        float acc2[4][4];
        gemm<8>(sH, 68, sW2, tg, tc, lane, cg, acc2);

        // ---- epilogue2 ----
        if (EDGE) {
            barp(barid);   // both warps finished reading H
#pragma unroll
            for (int nb = 0; nb < 4; ++nb) {
                const int col = cg * 32 + nb * 8 + tc * 2;
                const float2 bi = *reinterpret_cast<const float2*>(sBb + col);
                *reinterpret_cast<float2*>(sH + tg * 68 + col) =
                    make_float2(acc2[nb][0] + bi.x, acc2[nb][1] + bi.y);
                *reinterpret_cast<float2*>(sH + (tg + 8) * 68 + col) =
                    make_float2(acc2[nb][2] + bi.x, acc2[nb][3] + bi.y);
            }
            barp(barid);   // D staged
            const int* rows = sRowR + (j % 3) * 16;
#pragma unroll
            for (int it = 0; it < 4; ++it) {
                const int i = it * 64 + pt;   // [0, 16*16)
                const int row = i >> 4, q = i & 15;
                const float4 v = *reinterpret_cast<const float4*>(sH + row * 68 + q * 4);
                red4(g_summed + (size_t)rows[row] * 64 + q * 4, v);
            }
        } else {
#pragma unroll
            for (int nb = 0; nb < 4; ++nb) {
                const int col = cg * 32 + nb * 8 + tc * 2;
                const float2 bi = *reinterpret_cast<const float2*>(sBb + col);
                *reinterpret_cast<float2*>(outp + (size_t)(base + tg) * 64 + col) =
                    make_float2(acc2[nb][0] + bi.x, acc2[nb][1] + bi.y);
                *reinterpret_cast<float2*>(outp + (size_t)(base + tg + 8) * 64 + col) =
                    make_float2(acc2[nb][2] + bi.x, acc2[nb][3] + bi.y);
            }
        }
        barp(barid);   // A refill + idx ring + D consumed: next iter safe
    }
}

// ---------------- launch ----------------------------------------------------------------
extern "C" void kernel_launch(void* const* d_in, const int* in_sizes, int n_in,
                              void* d_out, int out_size) {
    const float* x   = reinterpret_cast<const float*>(d_in[0]);
    const void*  ei  = d_in[1];
    const float* ea  = reinterpret_cast<const float*>(d_in[2]);
    const float* W1a = reinterpret_cast<const float*>(d_in[5]);
    const float* b1a = reinterpret_cast<const float*>(d_in[6]);
    const float* W1b = reinterpret_cast<const float*>(d_in[7]);
    const float* b1b = reinterpret_cast<const float*>(d_in[8]);
    const float* W2a = reinterpret_cast<const float*>(d_in[9]);
    const float* b2a = reinterpret_cast<const float*>(d_in[10]);
    const float* W2b = reinterpret_cast<const float*>(d_in[11]);
    const float* b2b = reinterpret_cast<const float*>(d_in[12]);
    float* out = reinterpret_cast<float*>(d_out);

    cudaFuncSetAttribute(gnn_pass<true>,
                         cudaFuncAttributeMaxDynamicSharedMemorySize, SMEM_BYTES);
    cudaFuncSetAttribute(gnn_pass<false>,
                         cudaFuncAttributeMaxDynamicSharedMemorySize, SMEM_BYTES);

    void* gs = nullptr; void* gc = nullptr;
    cudaGetSymbolAddress(&gs, g_summed);
    cudaGetSymbolAddress(&gc, g_counts);
    cudaMemsetAsync(gs, 0, (size_t)N_NODES * 64 * sizeof(float));
    cudaMemsetAsync(gc, 0, (size_t)N_NODES * sizeof(float));

    gnn_pass<true><<<NBLK, NTH, SMEM_BYTES>>>(x, ei, ea, W1a, b1a, W1b, b1b, nullptr);
    gnn_pass<false><<<NBLK, NTH, SMEM_BYTES>>>(x, nullptr, nullptr,
                                               W2a, b2a, W2b, b2b, out);
}

// round 6
// speedup vs baseline: 3.6965x; 1.3754x over previous
#include <cuda_runtime.h>
#include <cstdint>

#define N_NODES 50000
#define N_EDGES 800000

// ---------------- scratch (static device allocation) ---------------------------
__device__ float g_summed[N_NODES * 64];   // scatter-sum of hidden h (pre-W1b)
__device__ float g_counts[N_NODES];
__device__ float g_agg[N_NODES * 64];      // (summed/cnt)·W1b + b1b

// ---------------- helpers -------------------------------------------------------
__device__ __forceinline__ uint32_t smem_u32(const void* p) {
    uint32_t a;
    asm("{ .reg .u64 t; cvta.to.shared.u64 t, %1; cvt.u32.u64 %0, t; }" : "=r"(a) : "l"(p));
    return a;
}
__device__ __forceinline__ uint32_t to_tf32(float f) {
    uint32_t r; asm("cvt.rna.tf32.f32 %0, %1;" : "=r"(r) : "f"(f)); return r;
}
__device__ __forceinline__ void red4(float* a, float4 v) {
    asm volatile("red.global.add.v4.f32 [%0], {%1,%2,%3,%4};"
                 :: "l"(a), "f"(v.x), "f"(v.y), "f"(v.z), "f"(v.w) : "memory");
}
__device__ __forceinline__ void barp(int id) {
    asm volatile("bar.sync %0, 64;" :: "r"(id) : "memory");
}
__device__ __forceinline__ void cp16(uint32_t dst, const void* src) {
    asm volatile("cp.async.cg.shared.global [%0], [%1], 16;" :: "r"(dst), "l"(src) : "memory");
}
__device__ __forceinline__ void cp_commit() {
    asm volatile("cp.async.commit_group;" ::: "memory");
}
template <int N> __device__ __forceinline__ void cp_wait() {
    asm volatile("cp.async.wait_group %0;" :: "n"(N) : "memory");
}
// m16n8k8 tf32 MMA. g = lane>>2, c = lane&3:
//   A: a0=A[g][c] a1=A[g+8][c] a2=A[g][c+4] a3=A[g+8][c+4]
//   B: b0=B[c][n] b1=B[c+4][n]  (n = lane>>2)
//   D: d0=D[g][2c] d1=D[g][2c+1] d2=D[g+8][2c] d3=D[g+8][2c+1]
__device__ __forceinline__ void mma8(float d[4], const uint32_t a[4],
                                     uint32_t b0, uint32_t b1) {
    asm("mma.sync.aligned.m16n8k8.row.col.f32.tf32.tf32.f32 "
        "{%0,%1,%2,%3}, {%4,%5,%6,%7}, {%8,%9}, {%0,%1,%2,%3};"
        : "+f"(d[0]), "+f"(d[1]), "+f"(d[2]), "+f"(d[3])
        : "r"(a[0]), "r"(a[1]), "r"(a[2]), "r"(a[3]), "r"(b0), "r"(b1));
}

// ---------------- weight fragment staging -------------------------------------------
// W [K x 64] row-major -> frags: sW[(kc*8+nb)*32 + lane] = {W[k0][n], W[k0+4][n]} (rna tf32)
template <int KC, int NTHR>
__device__ __forceinline__ void stage_w(uint2* sW, const float* __restrict__ W, int tid) {
    for (int i = tid; i < KC * 256; i += NTHR) {
        const int kc = i >> 8, nb = (i >> 5) & 7, t = i & 31;
        const int k0 = kc * 8 + (t & 3), n = nb * 8 + (t >> 2);
        uint2 fr;
        fr.x = to_tf32(W[k0 * 64 + n]);
        fr.y = to_tf32(W[(k0 + 4) * 64 + n]);
        sW[i] = fr;
    }
}

// ---------------- GEMM core: warp = 16 rows x 32 cols -------------------------------
template <int KC>
__device__ __forceinline__ void gemm(const float* __restrict__ sIn, int lds,
                                     const uint2* __restrict__ sWf,
                                     int tg, int tc, int lane, int cg, float acc[4][4]) {
#pragma unroll
    for (int nb = 0; nb < 4; ++nb)
#pragma unroll
        for (int j = 0; j < 4; ++j) acc[nb][j] = 0.0f;
    const float* p0 = sIn + tg * lds;
#pragma unroll 4
    for (int kc = 0; kc < KC; ++kc) {
        const float* q = p0 + kc * 8 + tc;
        uint32_t a[4];
        a[0] = __float_as_uint(q[0]);
        a[1] = __float_as_uint(q[8 * lds]);
        a[2] = __float_as_uint(q[4]);
        a[3] = __float_as_uint(q[8 * lds + 4]);
#pragma unroll
        for (int nb = 0; nb < 4; ++nb) {
            const uint2 B = sWf[(kc * 8 + cg * 4 + nb) * 32 + lane];
            mma8(acc[nb], a, B.x, B.y);
        }
    }
}

// =====================================================================================
// EDGE PASS: h = relu([x[col] || ea] @ W1a + b1a); red-scatter h; count degrees.
// 704 threads = 11 warp-pairs, 1 block/SM, double-buffered cp.async gather.
// =====================================================================================
#define ENT 704
#define EPAIRS 11
// smem floats: W1 frags 8192 | ba 64 | pairs at 8256, stride 4352:
//   A0 2112 (16x132) | A1 2112 | ringRow 64 int | ringCol 64 int   (ring of 4 x 16)
#define E_SMEM_F (8256 + EPAIRS * 4352)
#define E_SMEM_B (E_SMEM_F * 4)

__device__ __forceinline__ void load_idx_e(const void* ei, bool is64, int tbase,
                                           int* rs, int* cs, int pt) {
    if (pt < 16) {
        const int ge = tbase + pt;
        int r, c;
        if (is64) {
            const long long* e64 = reinterpret_cast<const long long*>(ei);
            r = (int)e64[ge]; c = (int)e64[N_EDGES + ge];
        } else {
            const int* e32 = reinterpret_cast<const int*>(ei);
            r = e32[ge]; c = e32[N_EDGES + ge];
        }
        atomicAdd(&g_counts[r], 1.0f);
        rs[pt] = r; cs[pt] = c;
    }
}

__device__ __forceinline__ void gather_cp_e(int base, const int* cols,
                                            const float* __restrict__ x,
                                            const float* __restrict__ ea,
                                            uint32_t a_dst, int pt) {
#pragma unroll
    for (int it = 0; it < 8; ++it) {
        const int i = it * 64 + pt;         // [0, 512)
        const int row = i >> 5, q = i & 31; // 16 rows x 32 16B-chunks
        const void* src;
        if (q < 16) src = (const char*)x  + ((size_t)cols[row] * 64 + q * 4) * 4;
        else        src = (const char*)ea + ((size_t)(base + row) * 64 + (q - 16) * 4) * 4;
        cp16(a_dst + (uint32_t)(row * 132 + q * 4) * 4, src);
    }
}

__global__ void __launch_bounds__(ENT, 1)
edge_pass(const float* __restrict__ x, const void* __restrict__ ei,
          const float* __restrict__ ea,
          const float* __restrict__ Wa, const float* __restrict__ ba)
{
    extern __shared__ float sm[];
    uint2* sW  = reinterpret_cast<uint2*>(sm);
    float* sBa = sm + 8192;
    const int tid = threadIdx.x, lane = tid & 31;
    const int tg = lane >> 2, tc = lane & 3;
    const int pr = tid >> 6, pt = tid & 63, cg = (tid >> 5) & 1;

    float* pb = sm + 8256 + pr * 4352;
    float* A0 = pb;
    float* A1 = pb + 2112;
    int* ringR = reinterpret_cast<int*>(pb + 4224);
    int* ringC = ringR + 64;
    const uint32_t aU[2] = {smem_u32(A0), smem_u32(A1)};
    const float* Ab[2] = {A0, A1};

    stage_w<16, ENT>(sW, Wa, tid);
    if (tid < 64) sBa[tid] = ba[tid];
    __syncthreads();

    // dtype sniff: int64 edge_index has zero high words for small nonneg values
    const int* e32 = reinterpret_cast<const int*>(ei);
    const bool is64 = ((e32[1] | e32[3] | e32[5] | e32[7]) == 0);

    const int NP = gridDim.x * EPAIRS;
    const int gp = blockIdx.x * EPAIRS + pr;
    const int ntiles = N_EDGES / 16;       // exact

    // prologue: idx tiles 0,1; cp.async tile 0
    load_idx_e(ei, is64, gp * 16, ringR, ringC, pt);
    if (gp + NP < ntiles)
        load_idx_e(ei, is64, (gp + NP) * 16, ringR + 16, ringC + 16, pt);
    barp(pr);
    gather_cp_e(gp * 16, ringC, x, ea, aU[0], pt);
    cp_commit();

    for (int j = 0; gp + j * NP < ntiles; ++j) {
        const bool hasN = gp + (j + 1) * NP < ntiles;
        // prefetch next tile; idx two ahead
        if (hasN) {
            gather_cp_e((gp + (j + 1) * NP) * 16, ringC + ((j + 1) & 3) * 16,
                        x, ea, aU[(j + 1) & 1], pt);
            cp_commit();
        }
        if (gp + (j + 2) * NP < ntiles)
            load_idx_e(ei, is64, (gp + (j + 2) * NP) * 16,
                       ringR + ((j + 2) & 3) * 16, ringC + ((j + 2) & 3) * 16, pt);
        if (hasN) cp_wait<1>(); else cp_wait<0>();
        barp(pr);   // cp.async data + idx ring visible pair-wide

        // GEMM1: [16x128] @ [128x64]
        float acc[4][4];
        gemm<16>(Ab[j & 1], 132, sW, tg, tc, lane, cg, acc);

        // epilogue: relu(+bias) -> shuffle-combine -> red4 from registers
        const int* rows = ringR + (j & 3) * 16;
        const int rnode = (tc & 1) ? rows[tg + 8] : rows[tg];
        float* dst = g_summed + (size_t)rnode * 64;
#pragma unroll
        for (int nb = 0; nb < 4; ++nb) {
            const int col0 = cg * 32 + nb * 8 + 2 * tc;
            const float2 bi = *reinterpret_cast<const float2*>(sBa + col0);
            const float h0 = fmaxf(acc[nb][0] + bi.x, 0.0f);
            const float h1 = fmaxf(acc[nb][1] + bi.y, 0.0f);
            const float h2 = fmaxf(acc[nb][2] + bi.x, 0.0f);
            const float h3 = fmaxf(acc[nb][3] + bi.y, 0.0f);
            const float p0 = __shfl_xor_sync(0xffffffffu, h0, 1);
            const float p1 = __shfl_xor_sync(0xffffffffu, h1, 1);
            const float p2 = __shfl_xor_sync(0xffffffffu, h2, 1);
            const float p3 = __shfl_xor_sync(0xffffffffu, h3, 1);
            if (tc & 1)   // row tg+8, cols col0-2 .. col0+1
                red4(dst + (col0 - 2), make_float4(p2, p3, h2, h3));
            else          // row tg, cols col0 .. col0+3
                red4(dst + col0, make_float4(h0, h1, p0, p1));
        }
        barp(pr);   // both warps past GEMM1 reads -> next cp.async target safe
    }
}

// =====================================================================================
// AGG PASS: g_agg[n] = (g_summed[n]/max(cnt,1)) @ W1b + (cnt>0 ? b1b : 0)
// =====================================================================================
#define ANT 512
#define APAIRS 8
// smem floats: W1b frags 4096 | bb 64 | pairs at 4160, stride 1104: A 16x68 + cnt 16
#define A_SMEM_F (4160 + APAIRS * 1104)
#define A_SMEM_B (A_SMEM_F * 4)

__global__ void __launch_bounds__(ANT, 1)
agg_pass(const float* __restrict__ Wb, const float* __restrict__ bb)
{
    extern __shared__ float sm[];
    uint2* sW  = reinterpret_cast<uint2*>(sm);
    float* sBb = sm + 4096;
    const int tid = threadIdx.x, lane = tid & 31;
    const int tg = lane >> 2, tc = lane & 3;
    const int pr = tid >> 6, pt = tid & 63, cg = (tid >> 5) & 1;

    float* sA   = sm + 4160 + pr * 1104;
    float* sCnt = sA + 1088;

    stage_w<8, ANT>(sW, Wb, tid);
    if (tid < 64) sBb[tid] = bb[tid];
    __syncthreads();

    const int NP = gridDim.x * APAIRS;
    const int gp = blockIdx.x * APAIRS + pr;
    const int ntiles = N_NODES / 16;   // exact

    for (int j = 0; gp + j * NP < ntiles; ++j) {
        const int base = (gp + j * NP) * 16;
        // gather scaled summed rows
#pragma unroll
        for (int it = 0; it < 4; ++it) {
            const int i = it * 64 + pt;          // [0, 256)
            const int row = i >> 4, q = i & 15;
            const int n = base + row;
            const float cnt = g_counts[n];
            const float s = 1.0f / fmaxf(cnt, 1.0f);
            float4 v = reinterpret_cast<const float4*>(g_summed)[(size_t)n * 16 + q];
            v.x *= s; v.y *= s; v.z *= s; v.w *= s;
            *reinterpret_cast<float4*>(sA + row * 68 + q * 4) = v;
            sCnt[row] = cnt;   // redundant same-value writes, benign
        }
        barp(pr);

        float acc[4][4];
        gemm<8>(sA, 68, sW, tg, tc, lane, cg, acc);

        const float ca = sCnt[tg], cb = sCnt[tg + 8];
#pragma unroll
        for (int nb = 0; nb < 4; ++nb) {
            const int col0 = cg * 32 + nb * 8 + 2 * tc;
            const float2 bi = *reinterpret_cast<const float2*>(sBb + col0);
            float2 oa = make_float2(acc[nb][0] + (ca > 0.0f ? bi.x : 0.0f),
                                    acc[nb][1] + (ca > 0.0f ? bi.y : 0.0f));
            float2 ob = make_float2(acc[nb][2] + (cb > 0.0f ? bi.x : 0.0f),
                                    acc[nb][3] + (cb > 0.0f ? bi.y : 0.0f));
            *reinterpret_cast<float2*>(g_agg + (size_t)(base + tg) * 64 + col0)     = oa;
            *reinterpret_cast<float2*>(g_agg + (size_t)(base + tg + 8) * 64 + col0) = ob;
        }
        barp(pr);   // sA/sCnt reuse safe
    }
}

// =====================================================================================
// NODE PASS: out = relu([x || g_agg] @ W2a + b2a) @ W2b + b2b
// =====================================================================================
#define NNT 704
#define NPAIRS 11
// smem floats: W2a frags 8192 | W2b frags 4096 | ba 64 | bb 64 | pairs at 12416,
//   stride 3200: A 16x132 (2112) + H 16x68 (1088)
#define N_SMEM_F (12416 + NPAIRS * 3200)
#define N_SMEM_B (N_SMEM_F * 4)

__global__ void __launch_bounds__(NNT, 1)
node_pass(const float* __restrict__ x,
          const float* __restrict__ Wa, const float* __restrict__ ba,
          const float* __restrict__ Wb, const float* __restrict__ bb,
          float* __restrict__ outp)
{
    extern __shared__ float sm[];
    uint2* sWa = reinterpret_cast<uint2*>(sm);
    uint2* sWb = reinterpret_cast<uint2*>(sm + 8192);
    float* sBa = sm + 12288;
    float* sBb = sm + 12352;
    const int tid = threadIdx.x, lane = tid & 31;
    const int tg = lane >> 2, tc = lane & 3;
    const int pr = tid >> 6, pt = tid & 63, cg = (tid >> 5) & 1;

    float* sA = sm + 12416 + pr * 3200;
    float* sH = sA + 2112;

    stage_w<16, NNT>(sWa, Wa, tid);
    stage_w<8, NNT>(sWb, Wb, tid);
    if (tid < 64) { sBa[tid] = ba[tid]; sBb[tid] = bb[tid]; }
    __syncthreads();

    const int NP = gridDim.x * NPAIRS;
    const int gp = blockIdx.x * NPAIRS + pr;
    const int ntiles = N_NODES / 16;   // exact

    for (int j = 0; gp + j * NP < ntiles; ++j) {
        const int base = (gp + j * NP) * 16;
#pragma unroll
        for (int it = 0; it < 8; ++it) {
            const int i = it * 64 + pt;
            const int row = i >> 5, q = i & 31;
            const int n = base + row;
            float4 v;
            if (q < 16) v = reinterpret_cast<const float4*>(x)[(size_t)n * 16 + q];
            else        v = reinterpret_cast<const float4*>(g_agg)[(size_t)n * 16 + (q - 16)];
            *reinterpret_cast<float4*>(sA + row * 132 + q * 4) = v;
        }
        barp(pr);

        float acc[4][4];
        gemm<16>(sA, 132, sWa, tg, tc, lane, cg, acc);

        // relu + b2a -> H (stride 68)
#pragma unroll
        for (int nb = 0; nb < 4; ++nb) {
            const int col0 = cg * 32 + nb * 8 + 2 * tc;
            const float2 bi = *reinterpret_cast<const float2*>(sBa + col0);
            *reinterpret_cast<float2*>(sH + tg * 68 + col0) =
                make_float2(fmaxf(acc[nb][0] + bi.x, 0.0f), fmaxf(acc[nb][1] + bi.y, 0.0f));
            *reinterpret_cast<float2*>(sH + (tg + 8) * 68 + col0) =
                make_float2(fmaxf(acc[nb][2] + bi.x, 0.0f), fmaxf(acc[nb][3] + bi.y, 0.0f));
        }
        barp(pr);

        float acc2[4][4];
        gemm<8>(sH, 68, sWb, tg, tc, lane, cg, acc2);

#pragma unroll
        for (int nb = 0; nb < 4; ++nb) {
            const int col0 = cg * 32 + nb * 8 + 2 * tc;
            const float2 bi = *reinterpret_cast<const float2*>(sBb + col0);
            *reinterpret_cast<float2*>(outp + (size_t)(base + tg) * 64 + col0) =
                make_float2(acc2[nb][0] + bi.x, acc2[nb][1] + bi.y);
            *reinterpret_cast<float2*>(outp + (size_t)(base + tg + 8) * 64 + col0) =
                make_float2(acc2[nb][2] + bi.x, acc2[nb][3] + bi.y);
        }
        barp(pr);   // sA/sH reuse safe
    }
}

// ---------------- launch ----------------------------------------------------------------
extern "C" void kernel_launch(void* const* d_in, const int* in_sizes, int n_in,
                              void* d_out, int out_size) {
    const float* x   = reinterpret_cast<const float*>(d_in[0]);
    const void*  ei  = d_in[1];
    const float* ea  = reinterpret_cast<const float*>(d_in[2]);
    const float* W1a = reinterpret_cast<const float*>(d_in[5]);
    const float* b1a = reinterpret_cast<const float*>(d_in[6]);
    const float* W1b = reinterpret_cast<const float*>(d_in[7]);
    const float* b1b = reinterpret_cast<const float*>(d_in[8]);
    const float* W2a = reinterpret_cast<const float*>(d_in[9]);
    const float* b2a = reinterpret_cast<const float*>(d_in[10]);
    const float* W2b = reinterpret_cast<const float*>(d_in[11]);
    const float* b2b = reinterpret_cast<const float*>(d_in[12]);
    float* out = reinterpret_cast<float*>(d_out);

    cudaFuncSetAttribute(edge_pass, cudaFuncAttributeMaxDynamicSharedMemorySize, E_SMEM_B);
    cudaFuncSetAttribute(agg_pass,  cudaFuncAttributeMaxDynamicSharedMemorySize, A_SMEM_B);
    cudaFuncSetAttribute(node_pass, cudaFuncAttributeMaxDynamicSharedMemorySize, N_SMEM_B);

    void* gs = nullptr; void* gc = nullptr;
    cudaGetSymbolAddress(&gs, g_summed);
    cudaGetSymbolAddress(&gc, g_counts);
    cudaMemsetAsync(gs, 0, (size_t)N_NODES * 64 * sizeof(float));
    cudaMemsetAsync(gc, 0, (size_t)N_NODES * sizeof(float));

    edge_pass<<<148, ENT, E_SMEM_B>>>(x, ei, ea, W1a, b1a);
    agg_pass<<<148, ANT, A_SMEM_B>>>(W1b, b1b);
    node_pass<<<148, NNT, N_SMEM_B>>>(x, W2a, b2a, W2b, b2b, out);
}